// round 8
// baseline (speedup 1.0000x reference)
#include <cuda_runtime.h>
#include <cstdint>

// DilateAttention: B=4, d=384 (12 heads x 32), H=W=64, 3x3 kernel, dilation 2, zero pad 2.
// q,k,v: [B, 384, 64, 64] f32. out: [B, 64, 64, 384] f32.
// Persistent CTAs (444 = 3/SM, one wave) pulling tiles from an atomic counter.
// Channel-halved pipeline: v restage overlaps QK/AV; NEXT tile's k is
// prefetched into dead plane halves during this tile's AV/epilogue, and next
// q is loaded into dead q registers after QK. Only tile #1's k wait is exposed.

#define NH  12
#define HD  32
#define HH  64
#define WW  64
#define TH  4
#define RR  8                   // TH + 4 halo rows
#define CC  68                  // 64 + 2 zero-pad each side
#define PS  (RR * CC)           // 544 floats per channel plane
#define TILE_FLOATS (HD * PS)   // 17408
#define SMEM_FLOATS (TILE_FLOATS + 8)
#define SLOT_IDX    (TILE_FLOATS + 4)   // int slot for next-tile broadcast
#define SCALE 0.17677669529663689f      // 32^-0.5
#define GRID    444
#define NTILES  768             // 16 h-tiles x 48 (b,head)

__device__ int g_tile_ctr;

__global__ void init_ctr_kernel() { g_tile_ctr = GRID; }

__device__ __forceinline__ void cp_async16(uint32_t saddr, const void* gptr) {
    asm volatile("cp.async.cg.shared.global [%0], [%1], 16;\n" :: "r"(saddr), "l"(gptr));
}
__device__ __forceinline__ void cp_commit() {
    asm volatile("cp.async.commit_group;\n" ::: "memory");
}
__device__ __forceinline__ void cp_wait0() {
    asm volatile("cp.async.wait_group 0;\n" ::: "memory");
}

__device__ __forceinline__ void decode_tile(int t, int& h0, size_t& base) {
    h0 = (t & 15) * TH;
    const int bh = t >> 4;            // 0..47
    const int b = bh / NH;
    const int head = bh - b * NH;
    base = ((size_t)b * 384 + (size_t)head * HD) * (HH * WW);
}

// Stage one halo row (or zero it if out of bounds). pads included.
__device__ __forceinline__ void stage_row(const float* g, float* tile,
                                          int rowoff, uint32_t s_int, bool inb) {
    if (inb) {
        #pragma unroll
        for (int j = 0; j < 16; j++) cp_async16(s_int + j * 16, g + j * 4);
        tile[rowoff + 0] = 0.f;  tile[rowoff + 1] = 0.f;
        tile[rowoff + 66] = 0.f; tile[rowoff + 67] = 0.f;
    } else {
        #pragma unroll
        for (int j = 0; j < CC; j++) tile[rowoff + j] = 0.f;
    }
}

__global__ __launch_bounds__(256, 3)
void dilate_attn_kernel(const float* __restrict__ q,
                        const float* __restrict__ k,
                        const float* __restrict__ v,
                        float* __restrict__ out)
{
    extern __shared__ float smem[];
    float* tile = smem + 2;   // interior cp.async dst 16B-aligned (row stride 272B)
    int* slot = (int*)smem + SLOT_IDX;

    const int tx  = threadIdx.x;       // 0..63 = w
    const int ty  = threadIdx.y;       // 0..3
    const int tid = ty * 64 + tx;

    // staging role: one halo row per thread; tid<128 <=> channel<16
    const int sc = tid >> 3;           // channel 0..31
    const int sr = tid & 7;            // halo row 0..7
    const int rowoff = (sc * RR + sr) * CC;
    const bool lowhalf = (sc < 16);
    const uint32_t s_int = (uint32_t)__cvta_generic_to_shared(&tile[rowoff + 2]);

    // ---- first tile: static assignment ----
    int t = blockIdx.x;                // 0..443 < 768
    int h0; size_t base;
    decode_tile(t, h0, base);
    int  gh  = h0 - 2 + sr;
    bool inb = (unsigned)gh < HH;

    // stage k(first) + commit
    stage_row(k + base + (size_t)sc * (HH * WW) + gh * WW, tile, rowoff, s_int, inb);
    cp_commit();

    // q(first) into registers
    float qr[HD];
    {
        const float* qp = q + base + (h0 + ty) * WW + tx;
        #pragma unroll
        for (int c = 0; c < HD; c++) qr[c] = qp[(size_t)c * (HH * WW)];
    }

    for (;;) {
        const float* gv = v + base + (size_t)sc * (HH * WW) + gh * WW;

        cp_wait0();
        __syncthreads();                       // bar1: k tile visible

        // ---- QK half 1: channels 0..15 (4 FFMA chains) ----
        float lg[9];
        #pragma unroll
        for (int kp = 0; kp < 9; kp++) {
            const int di = kp / 3;
            const int dj = kp - di * 3;
            const float* kr = &tile[(ty + 2 * di) * CC + tx + 2 * dj];
            float d0 = 0.f, d1 = 0.f, d2 = 0.f, d3 = 0.f;
            #pragma unroll
            for (int c = 0; c < 16; c += 4) {
                d0 = fmaf(qr[c],     kr[(c)     * PS], d0);
                d1 = fmaf(qr[c + 1], kr[(c + 1) * PS], d1);
                d2 = fmaf(qr[c + 2], kr[(c + 2) * PS], d2);
                d3 = fmaf(qr[c + 3], kr[(c + 3) * PS], d3);
            }
            lg[kp] = (d0 + d1) + (d2 + d3);
        }

        __syncthreads();                       // bar2: k planes 0-15 dead
        if (lowhalf) {                         // restage v ch0-15 now
            if (inb) {
                #pragma unroll
                for (int j = 0; j < 16; j++) cp_async16(s_int + j * 16, gv + j * 4);
            }
            cp_commit();
        }

        // ---- QK half 2: channels 16..31 (overlaps v-low copy) ----
        #pragma unroll
        for (int kp = 0; kp < 9; kp++) {
            const int di = kp / 3;
            const int dj = kp - di * 3;
            const float* kr = &tile[16 * PS + (ty + 2 * di) * CC + tx + 2 * dj];
            float d0 = 0.f, d1 = 0.f, d2 = 0.f, d3 = 0.f;
            #pragma unroll
            for (int c = 0; c < 16; c += 4) {
                d0 = fmaf(qr[16 + c],     kr[(c)     * PS], d0);
                d1 = fmaf(qr[16 + c + 1], kr[(c + 1) * PS], d1);
                d2 = fmaf(qr[16 + c + 2], kr[(c + 2) * PS], d2);
                d3 = fmaf(qr[16 + c + 3], kr[(c + 3) * PS], d3);
            }
            lg[kp] = (lg[kp] + (d0 + d1) + (d2 + d3)) * SCALE;
        }

        // ---- softmax over 9 ----
        float m = lg[0];
        #pragma unroll
        for (int kp = 1; kp < 9; kp++) m = fmaxf(m, lg[kp]);
        float p[9];
        float s = 0.f;
        #pragma unroll
        for (int kp = 0; kp < 9; kp++) { p[kp] = __expf(lg[kp] - m); s += p[kp]; }
        const float inv = __fdividef(1.f, s);

        // claim next tile (thread 0), broadcast through smem
        if (tid == 0) *slot = atomicAdd(&g_tile_ctr, 1);
        __syncthreads();                       // bar3: k planes 16-31 dead, slot visible
        const int nt = *slot;
        const bool more = (nt < NTILES);

        int h0n = 0; size_t basen = 0; int ghn = 0; bool inbn = false;
        const float* gkn = k;
        if (more) {
            decode_tile(nt, h0n, basen);
            ghn  = h0n - 2 + sr;
            inbn = (unsigned)ghn < HH;
            gkn  = k + basen + (size_t)sc * (HH * WW) + ghn * WW;
            // q(next) into the now-dead qr registers (hides behind AV)
            const float* qp = q + basen + (h0n + ty) * WW + tx;
            #pragma unroll
            for (int c = 0; c < HD; c++) qr[c] = qp[(size_t)c * (HH * WW)];
        }

        if (!lowhalf) {                        // restage v ch16-31
            if (inb) {
                #pragma unroll
                for (int j = 0; j < 16; j++) cp_async16(s_int + j * 16, gv + j * 4);
            }
            cp_commit();
        }

        if (lowhalf) cp_wait0();               // own v-low done
        __syncthreads();                       // bar4: v planes 0-15 visible

        // ---- AV half 1: channels 0..15 ----
        float acc[HD];
        #pragma unroll
        for (int c = 0; c < HD; c++) acc[c] = 0.f;
        #pragma unroll
        for (int kp = 0; kp < 9; kp++) {
            const int di = kp / 3;
            const int dj = kp - di * 3;
            const float pw = p[kp];
            const float* vr = &tile[(ty + 2 * di) * CC + tx + 2 * dj];
            #pragma unroll
            for (int c = 0; c < 16; c++)
                acc[c] = fmaf(pw, vr[c * PS], acc[c]);
        }

        if (!lowhalf) cp_wait0();              // own v-high done
        __syncthreads();                       // bar5: v 16-31 visible, v 0-15 dead

        // prefetch k(next) ch0-15 into dead planes (overlaps AV2 + epilogue)
        if (more && lowhalf) {
            stage_row(gkn, tile, rowoff, s_int, inbn);
            cp_commit();
        }

        // ---- AV half 2: channels 16..31 ----
        #pragma unroll
        for (int kp = 0; kp < 9; kp++) {
            const int di = kp / 3;
            const int dj = kp - di * 3;
            const float pw = p[kp];
            const float* vr = &tile[16 * PS + (ty + 2 * di) * CC + tx + 2 * dj];
            #pragma unroll
            for (int c = 0; c < 16; c++)
                acc[16 + c] = fmaf(pw, vr[c * PS], acc[16 + c]);
        }

        __syncthreads();                       // bar6: v planes 16-31 dead

        // ---- transpose through planes 16-31 region for coalesced stores ----
        float* ts = tile + 16 * PS;            // 8704..17152 < 17408 (8448 used)
        #pragma unroll
        for (int c = 0; c < HD; c++)
            ts[tid * 33 + c] = acc[c] * inv;
        __syncwarp();                          // each warp reads only its own 32 pixels

        const int lane  = tid & 31;            // becomes channel
        const int wbase = tid & ~31;
        {
            const int bh2  = t >> 4;
            const int b2   = bh2 / NH;
            const int head2 = bh2 - b2 * NH;
            #pragma unroll 4
            for (int pp = 0; pp < 32; pp++) {
                const int pid = wbase + pp;
                const int h2 = h0 + (pid >> 6);
                const int w2 = pid & 63;
                out[(((size_t)b2 * HH + h2) * WW + w2) * 384
                    + (size_t)head2 * HD + lane] = ts[pid * 33 + lane];
            }
        }

        __syncthreads();                       // bar7: stores read ts; scratch dead

        if (!more) break;

        // prefetch k(next) ch16-31 (region just freed from scratch)
        if (!lowhalf) {
            stage_row(gkn, tile, rowoff, s_int, inbn);
            cp_commit();
        }

        t = nt; h0 = h0n; base = basen; gh = ghn; inb = inbn;
    }
}

extern "C" void kernel_launch(void* const* d_in, const int* in_sizes, int n_in,
                              void* d_out, int out_size)
{
    const float* q = (const float*)d_in[0];
    const float* k = (const float*)d_in[1];
    const float* v = (const float*)d_in[2];
    float* out = (float*)d_out;

    init_ctr_kernel<<<1, 1>>>();

    const int smem_bytes = SMEM_FLOATS * sizeof(float);   // 69664
    cudaFuncSetAttribute(dilate_attn_kernel,
                         cudaFuncAttributeMaxDynamicSharedMemorySize, smem_bytes);

    dim3 block(64, 4, 1);
    dilate_attn_kernel<<<GRID, block, smem_bytes>>>(q, k, v, out);
}

// round 9
// speedup vs baseline: 1.0872x; 1.0872x over previous
#include <cuda_runtime.h>
#include <cstdint>

// DilateAttention: B=4, d=384 (12 heads x 32), H=W=64, 3x3 kernel, dilation 2, zero pad 2.
// q,k,v: [B, 384, 64, 64] f32. out: [B, 64, 64, 384] f32.
// R7 pipeline + channel-pair packing: smem tile stored as [pair][row][col]{c,c+1}
// so one LDS.64 feeds one fma.rn.f32x2 (2 channels per instruction).

#define NH  12
#define HD  32
#define HH  64
#define WW  64
#define TH  4
#define RR  8                     // TH + 4 halo rows
#define CC  68                    // 64 cols + 2 zero-pad each side
#define PS2 (RR * CC)             // 544 float2 per pair-plane
#define NPAIR 16
#define TILE_F2 (NPAIR * PS2)     // 8704 float2 = 69632 B
#define SCALE 0.17677669529663689f

__device__ __forceinline__ uint64_t pack2(float lo, float hi) {
    uint64_t r; asm("mov.b64 %0, {%1, %2};" : "=l"(r) : "f"(lo), "f"(hi)); return r;
}
__device__ __forceinline__ void unpack2(uint64_t v, float& lo, float& hi) {
    asm("mov.b64 {%0, %1}, %2;" : "=f"(lo), "=f"(hi) : "l"(v));
}
__device__ __forceinline__ void ffma2(uint64_t& d, uint64_t a, uint64_t b) {
    asm("fma.rn.f32x2 %0, %1, %2, %0;" : "+l"(d) : "l"(a), "l"(b));
}

// stage one half-row (32 cols) of a channel PAIR, interleaved {c,c+1} per col
__device__ __forceinline__ void stage_pair_half(const float* g0, float2* dst) {
    const float* g1 = g0 + (HH * WW);          // channel c+1
    #pragma unroll
    for (int j = 0; j < 8; j++) {
        const float4 a = *(const float4*)(g0 + 4 * j);
        const float4 b = *(const float4*)(g1 + 4 * j);
        *(float4*)(dst + 4 * j)     = make_float4(a.x, b.x, a.y, b.y);
        *(float4*)(dst + 4 * j + 2) = make_float4(a.z, b.z, a.w, b.w);
    }
}

__global__ __launch_bounds__(256, 3)
void dilate_attn_kernel(const float* __restrict__ q,
                        const float* __restrict__ k,
                        const float* __restrict__ v,
                        float* __restrict__ out)
{
    extern __shared__ float2 t2[];             // [NPAIR][RR][CC] float2

    const int tx  = threadIdx.x;               // 0..63 = w
    const int ty  = threadIdx.y;               // 0..3
    const int tid = ty * 64 + tx;

    const int h0   = blockIdx.x * TH;
    const int bh   = blockIdx.y;               // 0..47
    const int b    = bh / NH;
    const int head = bh - b * NH;
    const size_t base = ((size_t)b * 384 + (size_t)head * HD) * (HH * WW);

    // staging role: (channel-pair, halo row, col half); warps 0-3 <=> pairs 0-7
    const int sp = tid >> 4;                   // pair 0..15
    const int sr = (tid >> 1) & 7;             // halo row 0..7
    const int hf = tid & 1;                    // col half
    const int gh = h0 - 2 + sr;
    const bool inb = (unsigned)gh < HH;
    const bool lowhalf = (sp < 8);
    const size_t goff = base + (size_t)(2 * sp) * (HH * WW) + gh * WW + hf * 32;
    float2* srow = t2 + sp * PS2 + sr * CC;    // this thread's staging row
    float2* sdst = srow + 2 + hf * 32;         // interior, 16B aligned

    // ---- stage k tile (pads + OOB zeros persist through the v restage) ----
    if (inb) {
        stage_pair_half(k + goff, sdst);
        if (hf == 0) *(float4*)(srow)      = make_float4(0.f, 0.f, 0.f, 0.f);
        else         *(float4*)(srow + 66) = make_float4(0.f, 0.f, 0.f, 0.f);
    } else {
        float4* zr = (float4*)(srow + hf * 34);
        #pragma unroll
        for (int j = 0; j < 17; j++) zr[j] = make_float4(0.f, 0.f, 0.f, 0.f);
    }

    // ---- q channel pairs into packed registers ----
    const int h = h0 + ty;
    uint64_t qp[NPAIR];
    {
        const float* qptr = q + base + h * WW + tx;
        #pragma unroll
        for (int pp = 0; pp < NPAIR; pp++)
            qp[pp] = pack2(qptr[(size_t)(2 * pp) * (HH * WW)],
                           qptr[(size_t)(2 * pp + 1) * (HH * WW)]);
    }

    __syncthreads();                           // bar1: k tile visible

    // ---- QK half 1: pair-planes 0..7 (packed, 4 scalar chains) ----
    float lg[9];
    #pragma unroll
    for (int kp = 0; kp < 9; kp++) {
        const int di = kp / 3;
        const int dj = kp - di * 3;
        const float2* kr = t2 + (ty + 2 * di) * CC + tx + 2 * dj;
        uint64_t a0 = 0, a1 = 0;
        #pragma unroll
        for (int pp = 0; pp < 8; pp += 2) {
            ffma2(a0, qp[pp],     *(const uint64_t*)(kr + (pp)     * PS2));
            ffma2(a1, qp[pp + 1], *(const uint64_t*)(kr + (pp + 1) * PS2));
        }
        float x0, x1, x2, x3;
        unpack2(a0, x0, x1); unpack2(a1, x2, x3);
        lg[kp] = (x0 + x1) + (x2 + x3);
    }

    __syncthreads();                           // bar2: pair-planes 0-7 dead
    if (lowhalf && inb) stage_pair_half(v + goff, sdst);   // restage v pairs 0-7

    // ---- QK half 2: pair-planes 8..15 ----
    #pragma unroll
    for (int kp = 0; kp < 9; kp++) {
        const int di = kp / 3;
        const int dj = kp - di * 3;
        const float2* kr = t2 + 8 * PS2 + (ty + 2 * di) * CC + tx + 2 * dj;
        uint64_t a0 = 0, a1 = 0;
        #pragma unroll
        for (int pp = 0; pp < 8; pp += 2) {
            ffma2(a0, qp[8 + pp],     *(const uint64_t*)(kr + (pp)     * PS2));
            ffma2(a1, qp[8 + pp + 1], *(const uint64_t*)(kr + (pp + 1) * PS2));
        }
        float x0, x1, x2, x3;
        unpack2(a0, x0, x1); unpack2(a1, x2, x3);
        lg[kp] = (lg[kp] + (x0 + x1) + (x2 + x3)) * SCALE;  // OOB: k==0 -> logit 0
    }

    // ---- softmax over 9 ----
    float m = lg[0];
    #pragma unroll
    for (int kp = 1; kp < 9; kp++) m = fmaxf(m, lg[kp]);
    float p[9];
    float s = 0.f;
    #pragma unroll
    for (int kp = 0; kp < 9; kp++) { p[kp] = __expf(lg[kp] - m); s += p[kp]; }
    const float inv = __fdividef(1.f, s);

    __syncthreads();                           // bar3: pair-planes 8-15 dead
    if (!lowhalf && inb) stage_pair_half(v + goff, sdst);  // restage v pairs 8-15

    __syncthreads();                           // bar4: v pairs 0-7 visible

    // ---- AV half 1: pair-planes 0..7 ----
    uint64_t acc2[NPAIR];
    #pragma unroll
    for (int pp = 0; pp < NPAIR; pp++) acc2[pp] = 0;
    #pragma unroll
    for (int kp = 0; kp < 9; kp++) {
        const int di = kp / 3;
        const int dj = kp - di * 3;
        const uint64_t pw2 = pack2(p[kp], p[kp]);
        const float2* vr = t2 + (ty + 2 * di) * CC + tx + 2 * dj;
        #pragma unroll
        for (int pp = 0; pp < 8; pp++)
            ffma2(acc2[pp], pw2, *(const uint64_t*)(vr + pp * PS2));
    }

    __syncthreads();                           // bar5: v pairs 8-15 visible

    // ---- AV half 2: pair-planes 8..15 ----
    #pragma unroll
    for (int kp = 0; kp < 9; kp++) {
        const int di = kp / 3;
        const int dj = kp - di * 3;
        const uint64_t pw2 = pack2(p[kp], p[kp]);
        const float2* vr = t2 + 8 * PS2 + (ty + 2 * di) * CC + tx + 2 * dj;
        #pragma unroll
        for (int pp = 0; pp < 8; pp++)
            ffma2(acc2[8 + pp], pw2, *(const uint64_t*)(vr + pp * PS2));
    }

    // ---- transpose through upper pair-planes for coalesced 128B stores ----
    __syncthreads();                           // bar6: v pairs 8-15 dead
    float* ts = (float*)(t2 + 8 * PS2);        // 8448 floats needed, 8704 avail
    #pragma unroll
    for (int pp = 0; pp < NPAIR; pp++) {
        float lo, hi;
        unpack2(acc2[pp], lo, hi);
        ts[tid * 33 + 2 * pp]     = lo * inv;
        ts[tid * 33 + 2 * pp + 1] = hi * inv;
    }
    __syncwarp();                              // each warp reads only its own 32 pixels

    const int lane  = tid & 31;                // becomes channel
    const int wbase = tid & ~31;
    #pragma unroll 4
    for (int pp = 0; pp < 32; pp++) {
        const int pid = wbase + pp;
        const int h2 = h0 + (pid >> 6);
        const int w2 = pid & 63;
        out[(((size_t)b * HH + h2) * WW + w2) * 384 + (size_t)head * HD + lane]
            = ts[pid * 33 + lane];
    }
}

extern "C" void kernel_launch(void* const* d_in, const int* in_sizes, int n_in,
                              void* d_out, int out_size)
{
    const float* q = (const float*)d_in[0];
    const float* k = (const float*)d_in[1];
    const float* v = (const float*)d_in[2];
    float* out = (float*)d_out;

    const int smem_bytes = TILE_F2 * sizeof(float2);   // 69632
    cudaFuncSetAttribute(dilate_attn_kernel,
                         cudaFuncAttributeMaxDynamicSharedMemorySize, smem_bytes);

    dim3 block(64, 4, 1);
    dim3 grid(HH / TH, 4 * NH, 1);            // (16, 48)
    dilate_attn_kernel<<<grid, block, smem_bytes>>>(q, k, v, out);
}

// round 10
// speedup vs baseline: 1.6093x; 1.4802x over previous
#include <cuda_runtime.h>
#include <cstdint>

// DilateAttention: B=4, d=384 (12 heads x 32), H=W=64, 3x3 kernel, dilation 2, zero pad 2.
// q,k,v: [B, 384, 64, 64] f32. out: [B, 64, 64, 384] f32.
// Pixel-pair f32x2: each thread computes pixels (w, w+1); their k/v neighbor
// values are adjacent floats in the UNCHANGED plane layout, so one LDS.64 +
// one fma.rn.f32x2 serves both pixels. Staging identical to R7 (cp.async).

#define NH  12
#define HD  32
#define HH  64
#define WW  64
#define TH  8
#define RR  12                    // TH + 4 halo rows
#define CC  68                    // 64 + 2 zero-pad each side
#define PS  (RR * CC)             // 816 floats per channel plane
#define PSU (PS / 2)              // 408 u64 per plane
#define TILE_FLOATS (HD * PS)     // 26112
#define SMEM_FLOATS (TILE_FLOATS + 4)
#define SCALE 0.17677669529663689f

__device__ __forceinline__ uint64_t pack2(float lo, float hi) {
    uint64_t r; asm("mov.b64 %0, {%1, %2};" : "=l"(r) : "f"(lo), "f"(hi)); return r;
}
__device__ __forceinline__ void unpack2(uint64_t v, float& lo, float& hi) {
    asm("mov.b64 {%0, %1}, %2;" : "=f"(lo), "=f"(hi) : "l"(v));
}
__device__ __forceinline__ void ffma2(uint64_t& d, uint64_t a, uint64_t b) {
    asm("fma.rn.f32x2 %0, %1, %2, %0;" : "+l"(d) : "l"(a), "l"(b));
}
__device__ __forceinline__ uint64_t fmul2(uint64_t a, uint64_t b) {
    uint64_t d; asm("mul.rn.f32x2 %0, %1, %2;" : "=l"(d) : "l"(a), "l"(b)); return d;
}

__device__ __forceinline__ void cp_async16(uint32_t saddr, const void* gptr) {
    asm volatile("cp.async.cg.shared.global [%0], [%1], 16;\n" :: "r"(saddr), "l"(gptr));
}
__device__ __forceinline__ void cp_commit() {
    asm volatile("cp.async.commit_group;\n" ::: "memory");
}
template<int N> __device__ __forceinline__ void cp_wait() {
    asm volatile("cp.async.wait_group %0;\n" :: "n"(N) : "memory");
}

// Stage one halo row of k (interior via cp.async, pads/OOB zeroed).
__device__ __forceinline__ void stage_k_row(const float* g, float* tile, int rowoff,
                                            uint32_t s, bool inb) {
    if (inb) {
        #pragma unroll
        for (int j = 0; j < 16; j++) cp_async16(s + j * 16, g + j * 4);
        tile[rowoff + 0] = 0.f;  tile[rowoff + 1] = 0.f;
        tile[rowoff + 66] = 0.f; tile[rowoff + 67] = 0.f;
    } else {
        #pragma unroll
        for (int j = 0; j < CC; j++) tile[rowoff + j] = 0.f;
    }
}
// Restage v: interior only (pads/OOB zeros persist from the k stage).
__device__ __forceinline__ void stage_v_row(const float* g, uint32_t s, bool inb) {
    if (inb) {
        #pragma unroll
        for (int j = 0; j < 16; j++) cp_async16(s + j * 16, g + j * 4);
    }
}

__global__ __launch_bounds__(256, 2)
void dilate_attn_kernel(const float* __restrict__ q,
                        const float* __restrict__ k,
                        const float* __restrict__ v,
                        float* __restrict__ out)
{
    extern __shared__ float smem[];
    float* tile = smem + 2;   // interior cp.async dst = rowoff*4+16 -> 16B aligned

    const int tid = threadIdx.x;           // 0..255
    const int ty  = tid >> 5;              // 0..7  pixel row in tile
    const int pi  = tid & 31;              // pixel pair index
    const int w   = pi * 2;                // even pixel column

    const int h0   = blockIdx.x * TH;
    const int bh   = blockIdx.y;           // 0..47
    const int b    = bh / NH;
    const int head = bh - b * NH;
    const size_t base = ((size_t)b * 384 + (size_t)head * HD) * (HH * WW);

    // staging rows: global row id = c*RR + sr  (384 rows; thread gets r0 and maybe r1)
    const int r0  = tid;
    const int sc0 = r0 / RR, sr0 = r0 - sc0 * RR;
    const int gh0 = h0 - 2 + sr0;
    const bool inb0 = (unsigned)gh0 < HH;
    const int ro0 = r0 * CC;
    const size_t g0 = base + (size_t)sc0 * (HH * WW) + gh0 * WW;
    const uint32_t s0 = (uint32_t)__cvta_generic_to_shared(&tile[ro0 + 2]);

    const bool has1 = (tid < 128);
    const int r1  = 256 + tid;
    const int sc1 = r1 / RR, sr1 = r1 - sc1 * RR;
    const int gh1 = h0 - 2 + sr1;
    const bool inb1 = has1 && ((unsigned)gh1 < HH);
    const int ro1 = r1 * CC;
    const size_t g1 = base + (size_t)sc1 * (HH * WW) + gh1 * WW;
    const uint32_t s1 = (uint32_t)__cvta_generic_to_shared(&tile[ro1 + 2]);

    // ---- stage k (group 1) ----
    stage_k_row(k + g0, tile, ro0, s0, inb0);
    if (has1) stage_k_row(k + g1, tile, ro1, s1, inb1);
    cp_commit();

    // ---- q: 32 channels x 2 pixels as packed float2 (coalesced LDG.64) ----
    const int h = h0 + ty;
    uint64_t q2[HD];
    {
        const uint64_t* qp = (const uint64_t*)(q + base + h * WW + w);
        #pragma unroll
        for (int c = 0; c < HD; c++) q2[c] = __ldg(qp + (size_t)c * 2048);
    }

    cp_wait<0>();
    __syncthreads();                       // bar1: k tile visible

    // ---- QK half 1: channels 0..15 (one packed chain per kp; 9 independent) ----
    uint64_t lg2[9];
    #pragma unroll
    for (int kp = 0; kp < 9; kp++) {
        const int di = kp / 3;
        const int dj = kp - di * 3;
        const uint64_t* kr =
            (const uint64_t*)(tile + (ty + 2 * di) * CC + w + 2 * dj);
        uint64_t a = 0;
        #pragma unroll
        for (int c = 0; c < 16; c++) ffma2(a, q2[c], kr[c * PSU]);
        lg2[kp] = a;
    }

    __syncthreads();                       // bar2: k planes 0-15 dead
    if (tid < 192) stage_v_row(v + g0, s0, inb0);   // v rows 0..191 (ch 0-15)
    cp_commit();                            // group 2 (vA) — uniform

    // ---- QK half 2: channels 16..31 (overlaps vA copy) ----
    #pragma unroll
    for (int kp = 0; kp < 9; kp++) {
        const int di = kp / 3;
        const int dj = kp - di * 3;
        const uint64_t* kr =
            (const uint64_t*)(tile + 16 * PS + (ty + 2 * di) * CC + w + 2 * dj);
        uint64_t a = lg2[kp];
        #pragma unroll
        for (int c = 0; c < 16; c++) ffma2(a, q2[16 + c], kr[c * PSU]);
        lg2[kp] = a;
    }

    // ---- softmax for both pixels ----
    float l0[9], l1[9];
    #pragma unroll
    for (int kp = 0; kp < 9; kp++) {
        unpack2(lg2[kp], l0[kp], l1[kp]);
        l0[kp] *= SCALE; l1[kp] *= SCALE;   // OOB neighbor: k==0 -> logit 0 (zero-pad)
    }
    float m0 = l0[0], m1 = l1[0];
    #pragma unroll
    for (int kp = 1; kp < 9; kp++) { m0 = fmaxf(m0, l0[kp]); m1 = fmaxf(m1, l1[kp]); }
    float sum0 = 0.f, sum1 = 0.f;
    uint64_t p2[9];
    #pragma unroll
    for (int kp = 0; kp < 9; kp++) {
        const float e0 = __expf(l0[kp] - m0);
        const float e1 = __expf(l1[kp] - m1);
        sum0 += e0; sum1 += e1;
        p2[kp] = pack2(e0, e1);
    }
    const uint64_t inv2 = pack2(__fdividef(1.f, sum0), __fdividef(1.f, sum1));

    __syncthreads();                       // bar3: k planes 16-31 dead
    if (tid >= 192) stage_v_row(v + g0, s0, inb0);      // v rows 192..255
    if (has1)       stage_v_row(v + g1, s1, inb1);      // v rows 256..383
    cp_commit();                            // group 3 (vB) — uniform

    cp_wait<1>();                           // groups K + vA complete
    __syncthreads();                       // bar4: v planes 0-15 visible

    // ---- AV half 1: channels 0..15 (16 independent packed chains) ----
    uint64_t acc2[HD];
    #pragma unroll
    for (int c = 0; c < HD; c++) acc2[c] = 0;
    #pragma unroll
    for (int kp = 0; kp < 9; kp++) {
        const int di = kp / 3;
        const int dj = kp - di * 3;
        const uint64_t* vr =
            (const uint64_t*)(tile + (ty + 2 * di) * CC + w + 2 * dj);
        #pragma unroll
        for (int c = 0; c < 16; c++) ffma2(acc2[c], p2[kp], vr[c * PSU]);
    }

    cp_wait<0>();                           // vB complete
    __syncthreads();                       // bar5: v planes 16-31 visible

    // ---- AV half 2: channels 16..31 ----
    #pragma unroll
    for (int kp = 0; kp < 9; kp++) {
        const int di = kp / 3;
        const int dj = kp - di * 3;
        const uint64_t* vr =
            (const uint64_t*)(tile + 16 * PS + (ty + 2 * di) * CC + w + 2 * dj);
        #pragma unroll
        for (int c = 0; c < 16; c++) ffma2(acc2[16 + c], p2[kp], vr[c * PSU]);
    }

    // ---- direct stores: 2 pixels x 128B contiguous (8 STG.128 each) ----
    const size_t ob = (((size_t)b * HH + h) * WW + w) * 384 + (size_t)head * HD;
    float4* d0 = (float4*)(out + ob);          // pixel w
    float4* d1 = (float4*)(out + ob + 384);    // pixel w+1
    #pragma unroll
    for (int i = 0; i < 8; i++) {
        float x0, y0, x1, y1, x2, y2, x3, y3;
        unpack2(fmul2(acc2[4 * i + 0], inv2), x0, y0);
        unpack2(fmul2(acc2[4 * i + 1], inv2), x1, y1);
        unpack2(fmul2(acc2[4 * i + 2], inv2), x2, y2);
        unpack2(fmul2(acc2[4 * i + 3], inv2), x3, y3);
        d0[i] = make_float4(x0, x1, x2, x3);
        d1[i] = make_float4(y0, y1, y2, y3);
    }
}

extern "C" void kernel_launch(void* const* d_in, const int* in_sizes, int n_in,
                              void* d_out, int out_size)
{
    const float* q = (const float*)d_in[0];
    const float* k = (const float*)d_in[1];
    const float* v = (const float*)d_in[2];
    float* out = (float*)d_out;

    const int smem_bytes = SMEM_FLOATS * sizeof(float);   // 104464
    cudaFuncSetAttribute(dilate_attn_kernel,
                         cudaFuncAttributeMaxDynamicSharedMemorySize, smem_bytes);

    dim3 block(256, 1, 1);
    dim3 grid(HH / TH, 4 * NH, 1);        // (8, 48)
    dilate_attn_kernel<<<grid, block, smem_bytes>>>(q, k, v, out);
}